// round 14
// baseline (speedup 1.0000x reference)
#include <cuda_runtime.h>
#include <math.h>

#define BATCH   4
#define SEQ     4096
#define HID     1280
#define NHEADS  20
#define HDIM    64
#define CDIM    2048
#define TTXT    77
#define TIP     20
#define TTOT    97
#define ATTN_SCALE 0.125f

// Scratch (device globals: no cudaMalloc allowed)
__device__ float g_q   [BATCH*SEQ*HID];            // Q projection
__device__ float g_attn[BATCH*SEQ*HID];            // attention output (pre-Wo)
__device__ float g_k   [BATCH*NHEADS*TTXT*HDIM];   // K heads  [b][h][t][d]
__device__ float g_v   [BATCH*NHEADS*TTXT*HDIM];   // V heads
__device__ float g_ipk [BATCH*NHEADS*TIP*HDIM];    // ip-K heads
__device__ float g_ipv [BATCH*NHEADS*TIP*HDIM];    // ip-V heads

// ---------------------------------------------------------------------------
// SGEMM (NT): C[m][n] = sum_k A[m*K+k] * B[n*K+k] (+ bias[n])
// 128x128 tile, BK=16, 256 threads, 8x8 per thread, double-buffered smem.
// Requires M%128==0, N%128==0, K%16==0.
// ---------------------------------------------------------------------------
__global__ __launch_bounds__(256)
void sgemm_nt_128(const float* __restrict__ A, const float* __restrict__ B,
                  const float* __restrict__ bias, float* __restrict__ C,
                  int M, int N, int K)
{
    __shared__ float As[2][16][128];
    __shared__ float Bs[2][16][128];

    const int tid = threadIdx.x;
    const int tx  = tid & 15;
    const int ty  = tid >> 4;
    const int m0  = blockIdx.y * 128;
    const int n0  = blockIdx.x * 128;
    const int lr  = tid >> 2;          // 0..63
    const int lc  = (tid & 3) * 4;     // 0,4,8,12

    const float* Ap = A + (size_t)(m0 + lr) * K + lc;
    const float* Bp = B + (size_t)(n0 + lr) * K + lc;
    const size_t strideA = (size_t)64 * K;

    float acc[8][8];
    #pragma unroll
    for (int i = 0; i < 8; i++)
        #pragma unroll
        for (int j = 0; j < 8; j++) acc[i][j] = 0.f;

    // prologue: tile 0
    {
        float4 a0 = *(const float4*)Ap;
        float4 a1 = *(const float4*)(Ap + strideA);
        float4 b0 = *(const float4*)Bp;
        float4 b1 = *(const float4*)(Bp + strideA);
        As[0][lc+0][lr]    = a0.x; As[0][lc+1][lr]    = a0.y; As[0][lc+2][lr]    = a0.z; As[0][lc+3][lr]    = a0.w;
        As[0][lc+0][lr+64] = a1.x; As[0][lc+1][lr+64] = a1.y; As[0][lc+2][lr+64] = a1.z; As[0][lc+3][lr+64] = a1.w;
        Bs[0][lc+0][lr]    = b0.x; Bs[0][lc+1][lr]    = b0.y; Bs[0][lc+2][lr]    = b0.z; Bs[0][lc+3][lr]    = b0.w;
        Bs[0][lc+0][lr+64] = b1.x; Bs[0][lc+1][lr+64] = b1.y; Bs[0][lc+2][lr+64] = b1.z; Bs[0][lc+3][lr+64] = b1.w;
    }
    __syncthreads();

    const int KT = K >> 4;
    for (int kt = 0; kt < KT; ++kt) {
        const int buf = kt & 1;
        float4 na0, na1, nb0, nb1;
        const bool more = (kt + 1) < KT;
        if (more) {
            const float* Ap2 = Ap + (kt + 1) * 16;
            const float* Bp2 = Bp + (kt + 1) * 16;
            na0 = *(const float4*)Ap2;
            na1 = *(const float4*)(Ap2 + strideA);
            nb0 = *(const float4*)Bp2;
            nb1 = *(const float4*)(Bp2 + strideA);
        }
        #pragma unroll
        for (int kk = 0; kk < 16; kk++) {
            float4 af0 = *(const float4*)(&As[buf][kk][ty * 4]);
            float4 af1 = *(const float4*)(&As[buf][kk][64 + ty * 4]);
            float4 bf0 = *(const float4*)(&Bs[buf][kk][tx * 4]);
            float4 bf1 = *(const float4*)(&Bs[buf][kk][64 + tx * 4]);
            float av[8] = {af0.x, af0.y, af0.z, af0.w, af1.x, af1.y, af1.z, af1.w};
            float bv[8] = {bf0.x, bf0.y, bf0.z, bf0.w, bf1.x, bf1.y, bf1.z, bf1.w};
            #pragma unroll
            for (int i = 0; i < 8; i++)
                #pragma unroll
                for (int j = 0; j < 8; j++)
                    acc[i][j] = fmaf(av[i], bv[j], acc[i][j]);
        }
        if (more) {
            const int nb = buf ^ 1;
            As[nb][lc+0][lr]    = na0.x; As[nb][lc+1][lr]    = na0.y; As[nb][lc+2][lr]    = na0.z; As[nb][lc+3][lr]    = na0.w;
            As[nb][lc+0][lr+64] = na1.x; As[nb][lc+1][lr+64] = na1.y; As[nb][lc+2][lr+64] = na1.z; As[nb][lc+3][lr+64] = na1.w;
            Bs[nb][lc+0][lr]    = nb0.x; Bs[nb][lc+1][lr]    = nb0.y; Bs[nb][lc+2][lr]    = nb0.z; Bs[nb][lc+3][lr]    = nb0.w;
            Bs[nb][lc+0][lr+64] = nb1.x; Bs[nb][lc+1][lr+64] = nb1.y; Bs[nb][lc+2][lr+64] = nb1.z; Bs[nb][lc+3][lr+64] = nb1.w;
            __syncthreads();
        }
    }

    float bv0[4] = {0.f, 0.f, 0.f, 0.f}, bv1[4] = {0.f, 0.f, 0.f, 0.f};
    if (bias) {
        #pragma unroll
        for (int j = 0; j < 4; j++) {
            bv0[j] = bias[n0 + tx * 4 + j];
            bv1[j] = bias[n0 + 64 + tx * 4 + j];
        }
    }
    #pragma unroll
    for (int i = 0; i < 8; i++) {
        const int m = m0 + ((i < 4) ? (ty * 4 + i) : (64 + ty * 4 + (i - 4)));
        float* crow = C + (size_t)m * N + n0;
        float4 o0 = make_float4(acc[i][0] + bv0[0], acc[i][1] + bv0[1],
                                acc[i][2] + bv0[2], acc[i][3] + bv0[3]);
        float4 o1 = make_float4(acc[i][4] + bv1[0], acc[i][5] + bv1[1],
                                acc[i][6] + bv1[2], acc[i][7] + bv1[3]);
        *(float4*)(crow + tx * 4)      = o0;
        *(float4*)(crow + 64 + tx * 4) = o1;
    }
}

// ---------------------------------------------------------------------------
// K/V projection: out[b][h][t][d] = sum_c ehs[b, toff+t, c] * W[h*64+d, c]
// One launch handles a weight pair (W0->out0, W1->out1) via blockIdx.z.
// BM=64, BN=64 (= one head), BK=16, 256 threads, 4x4 per thread. M masked.
// ---------------------------------------------------------------------------
__global__ __launch_bounds__(256)
void kv_gemm(const float* __restrict__ ehs,
             const float* __restrict__ W0, const float* __restrict__ W1,
             float* __restrict__ out0, float* __restrict__ out1,
             int rows, int toff)
{
    __shared__ float As[16][64];
    __shared__ float Bs[16][64];

    const int Mtot = BATCH * rows;
    const float* W = blockIdx.z ? W1 : W0;
    float* outp    = blockIdx.z ? out1 : out0;
    const int m0 = blockIdx.x * 64;
    const int h  = blockIdx.y;
    const int tid = threadIdx.x;
    const int tx = tid & 15, ty = tid >> 4;
    const int lr = tid >> 2, lc = (tid & 3) * 4;

    const float* arow = nullptr;
    const int gr = m0 + lr;
    if (gr < Mtot) {
        const int bb = gr / rows, t = gr - bb * rows;
        arow = ehs + (size_t)(bb * TTOT + toff + t) * CDIM + lc;
    }
    const float* brow = W + (size_t)(h * 64 + lr) * CDIM + lc;

    float acc[4][4] = {};
    for (int kt = 0; kt < CDIM / 16; ++kt) {
        float4 av = arow ? *(const float4*)(arow + kt * 16) : make_float4(0.f, 0.f, 0.f, 0.f);
        float4 bv = *(const float4*)(brow + kt * 16);
        __syncthreads();
        As[lc+0][lr] = av.x; As[lc+1][lr] = av.y; As[lc+2][lr] = av.z; As[lc+3][lr] = av.w;
        Bs[lc+0][lr] = bv.x; Bs[lc+1][lr] = bv.y; Bs[lc+2][lr] = bv.z; Bs[lc+3][lr] = bv.w;
        __syncthreads();
        #pragma unroll
        for (int kk = 0; kk < 16; kk++) {
            float4 a  = *(const float4*)(&As[kk][ty * 4]);
            float4 b4 = *(const float4*)(&Bs[kk][tx * 4]);
            float avv[4] = {a.x, a.y, a.z, a.w};
            float bvv[4] = {b4.x, b4.y, b4.z, b4.w};
            #pragma unroll
            for (int i = 0; i < 4; i++)
                #pragma unroll
                for (int j = 0; j < 4; j++)
                    acc[i][j] = fmaf(avv[i], bvv[j], acc[i][j]);
        }
    }
    #pragma unroll
    for (int i = 0; i < 4; i++) {
        const int gr2 = m0 + ty * 4 + i;
        if (gr2 < Mtot) {
            const int bb = gr2 / rows, t = gr2 - bb * rows;
            float4 o = make_float4(acc[i][0], acc[i][1], acc[i][2], acc[i][3]);
            *(float4*)(outp + (size_t)((bb * NHEADS + h) * rows + t) * HDIM + tx * 4) = o;
        }
    }
}

// ---------------------------------------------------------------------------
// Fused attention. One block = 64 queries for one (b, h).
// All keys fit in smem (77 text / 20 ip). Blend is computed by running the
// score/softmax/PV phase multiple times with different (q,k) but the same V,
// accumulating with the blend weight folded into the softmax normalization.
//   b even: out = softmax(q_b k_b) @ v_b
//   b odd : out = 0.5*(P_b + P_{b-1}) @ v_b + 0.5*(ipP_b + ipP_{b-1}) @ ipv_b
// ---------------------------------------------------------------------------
#define ATTN_SMEM ((64*65 + 64*81 + 77*64 + 64*81) * 4)

__global__ __launch_bounds__(256)
void attn_kernel()
{
    extern __shared__ float sm[];
    float* Qt = sm;                 // [64 d][65]   (q transposed, padded)
    float* Kt = Qt + 64 * 65;       // [64 d][81]   (k transposed, padded, zero-filled t>=nt)
    float* Vs = Kt + 64 * 81;       // [77 t][64 d]
    float* Ss = Vs + 77 * 64;       // [64 q][81 t] (scores -> probs)

    const int s0 = blockIdx.x * 64;
    const int h  = blockIdx.y;
    const int b  = blockIdx.z;
    const int tid = threadIdx.x;
    const int tx = tid & 15;        // -> 5 t's (scores), 4 d's (PV)
    const int ty = tid >> 4;        // -> 4 q's

    float acc[4][4] = {};

    auto load_v = [&](const float* vg, int nt) {
        __syncthreads();
        for (int i = tid; i < nt * 64; i += 256) Vs[i] = vg[i];
    };

    auto phase = [&](const float* qg, const float* kg, int nt, float w) {
        __syncthreads();
        for (int i = tid; i < 64 * 64; i += 256) {
            const int q = i >> 6, d = i & 63;
            Qt[d * 65 + q] = qg[(size_t)q * HID + d];
        }
        for (int i = tid; i < 80 * 64; i += 256) {
            const int t = i >> 6, d = i & 63;
            Kt[d * 81 + t] = (t < nt) ? kg[t * 64 + d] : 0.f;
        }
        __syncthreads();

        // scores: S[q][t] = scale * dot_d(Q, K)
        if (tx * 5 < nt) {
            float sacc[4][5];
            #pragma unroll
            for (int i = 0; i < 4; i++)
                #pragma unroll
                for (int j = 0; j < 5; j++) sacc[i][j] = 0.f;
            for (int d = 0; d < 64; d++) {
                const float q0 = Qt[d * 65 + ty * 4 + 0];
                const float q1 = Qt[d * 65 + ty * 4 + 1];
                const float q2 = Qt[d * 65 + ty * 4 + 2];
                const float q3 = Qt[d * 65 + ty * 4 + 3];
                #pragma unroll
                for (int j = 0; j < 5; j++) {
                    const float kv = Kt[d * 81 + tx * 5 + j];
                    sacc[0][j] = fmaf(q0, kv, sacc[0][j]);
                    sacc[1][j] = fmaf(q1, kv, sacc[1][j]);
                    sacc[2][j] = fmaf(q2, kv, sacc[2][j]);
                    sacc[3][j] = fmaf(q3, kv, sacc[3][j]);
                }
            }
            #pragma unroll
            for (int j = 0; j < 5; j++) {
                const int t = tx * 5 + j;
                if (t < nt) {
                    #pragma unroll
                    for (int i = 0; i < 4; i++)
                        Ss[(ty * 4 + i) * 81 + t] = sacc[i][j] * ATTN_SCALE;
                }
            }
        }
        __syncthreads();

        // softmax (4 threads per row), weight w folded into normalization
        {
            const int row = tid >> 2, sub = tid & 3;
            float* srow = Ss + row * 81;
            float m = -1e30f;
            for (int t = sub; t < nt; t += 4) m = fmaxf(m, srow[t]);
            m = fmaxf(m, __shfl_xor_sync(0xffffffffu, m, 1));
            m = fmaxf(m, __shfl_xor_sync(0xffffffffu, m, 2));
            float l = 0.f;
            for (int t = sub; t < nt; t += 4) {
                const float e = __expf(srow[t] - m);
                srow[t] = e;
                l += e;
            }
            l += __shfl_xor_sync(0xffffffffu, l, 1);
            l += __shfl_xor_sync(0xffffffffu, l, 2);
            const float inv = w / l;
            for (int t = sub; t < nt; t += 4) srow[t] *= inv;
        }
        __syncthreads();

        // PV accumulate
        for (int t = 0; t < nt; t++) {
            const float4 v = *(const float4*)(Vs + t * 64 + tx * 4);
            #pragma unroll
            for (int i = 0; i < 4; i++) {
                const float p = Ss[(ty * 4 + i) * 81 + t];
                acc[i][0] = fmaf(p, v.x, acc[i][0]);
                acc[i][1] = fmaf(p, v.y, acc[i][1]);
                acc[i][2] = fmaf(p, v.z, acc[i][2]);
                acc[i][3] = fmaf(p, v.w, acc[i][3]);
            }
        }
    };

    const float* qb = g_q + (size_t)(b * SEQ + s0) * HID + h * HDIM;
    const float* kb = g_k + (size_t)(b * NHEADS + h) * TTXT * HDIM;
    const float* vb = g_v + (size_t)(b * NHEADS + h) * TTXT * HDIM;
    const bool odd = (b & 1);

    load_v(vb, TTXT);
    phase(qb, kb, TTXT, odd ? 0.5f : 1.0f);
    if (odd) {
        const float* qa = g_q + (size_t)((b - 1) * SEQ + s0) * HID + h * HDIM;
        phase(qa, g_k + (size_t)((b - 1) * NHEADS + h) * TTXT * HDIM, TTXT, 0.5f);
        load_v(g_ipv + (size_t)(b * NHEADS + h) * TIP * HDIM, TIP);
        phase(qb, g_ipk + (size_t)(b * NHEADS + h) * TIP * HDIM, TIP, 0.5f);
        phase(qa, g_ipk + (size_t)((b - 1) * NHEADS + h) * TIP * HDIM, TIP, 0.5f);
    }

    float* op = g_attn + (size_t)(b * SEQ + s0) * HID + h * HDIM;
    #pragma unroll
    for (int i = 0; i < 4; i++) {
        float4 o = make_float4(acc[i][0], acc[i][1], acc[i][2], acc[i][3]);
        *(float4*)(op + (size_t)(ty * 4 + i) * HID + tx * 4) = o;
    }
}

// ---------------------------------------------------------------------------
extern "C" void kernel_launch(void* const* d_in, const int* in_sizes, int n_in,
                              void* d_out, int out_size)
{
    const float* hs   = (const float*)d_in[0];
    const float* ehs  = (const float*)d_in[1];
    const float* Wq   = (const float*)d_in[2];
    const float* Wk   = (const float*)d_in[3];
    const float* Wv   = (const float*)d_in[4];
    const float* Wkip = (const float*)d_in[5];
    const float* Wvip = (const float*)d_in[6];
    const float* Wo   = (const float*)d_in[7];
    const float* bo   = (const float*)d_in[8];
    float* out = (float*)d_out;

    float *qp, *ap, *kp, *vp, *ikp, *ivp;
    cudaGetSymbolAddress((void**)&qp,  g_q);
    cudaGetSymbolAddress((void**)&ap,  g_attn);
    cudaGetSymbolAddress((void**)&kp,  g_k);
    cudaGetSymbolAddress((void**)&vp,  g_v);
    cudaGetSymbolAddress((void**)&ikp, g_ipk);
    cudaGetSymbolAddress((void**)&ivp, g_ipv);

    cudaFuncSetAttribute(attn_kernel, cudaFuncAttributeMaxDynamicSharedMemorySize, ATTN_SMEM);

    const dim3 gBig(HID / 128, (BATCH * SEQ) / 128);   // (10, 128)

    // 1) Q = hs @ Wq^T
    sgemm_nt_128<<<gBig, 256>>>(hs, Wq, nullptr, qp, BATCH * SEQ, HID, HID);

    // 2) K/V and ip-K/ip-V projections (head-major outputs)
    kv_gemm<<<dim3(5, NHEADS, 2), 256>>>(ehs, Wk,   Wv,   kp,  vp,  TTXT, 0);
    kv_gemm<<<dim3(2, NHEADS, 2), 256>>>(ehs, Wkip, Wvip, ikp, ivp, TIP,  TTXT);

    // 3) fused attention (text + ip branches, cross-batch blend)
    attn_kernel<<<dim3(SEQ / 64, NHEADS, BATCH), 256, ATTN_SMEM>>>();

    // 4) out = attn @ Wo^T + bo
    sgemm_nt_128<<<gBig, 256>>>(ap, Wo, bo, out, BATCH * SEQ, HID, HID);
}

// round 15
// speedup vs baseline: 1.0012x; 1.0012x over previous
#include <cuda_runtime.h>
#include <math.h>

#define BATCH   4
#define SEQ     4096
#define HID     1280
#define NHEADS  20
#define HDIM    64
#define CDIM    2048
#define TTXT    77
#define TIP     20
#define TTOT    97
#define ATTN_SCALE 0.125f

// Scratch (device globals: no cudaMalloc allowed)
__device__ float g_q   [BATCH*SEQ*HID];            // Q projection
__device__ float g_attn[BATCH*SEQ*HID];            // attention output (pre-Wo)
__device__ float g_k   [BATCH*NHEADS*TTXT*HDIM];   // K heads  [b][h][t][d]
__device__ float g_v   [BATCH*NHEADS*TTXT*HDIM];   // V heads
__device__ float g_ipk [BATCH*NHEADS*TIP*HDIM];    // ip-K heads
__device__ float g_ipv [BATCH*NHEADS*TIP*HDIM];    // ip-V heads

// ---------------------------------------------------------------------------
// SGEMM (NT): C[m][n] = sum_k A[m*K+k] * B[n*K+k] (+ bias[n])
// 128x128 tile, BK=16, 256 threads, 8x8 per thread, double-buffered smem.
// Requires M%128==0, N%128==0, K%16==0.
// ---------------------------------------------------------------------------
__global__ __launch_bounds__(256)
void sgemm_nt_128(const float* __restrict__ A, const float* __restrict__ B,
                  const float* __restrict__ bias, float* __restrict__ C,
                  int M, int N, int K)
{
    __shared__ float As[2][16][128];
    __shared__ float Bs[2][16][128];

    const int tid = threadIdx.x;
    const int tx  = tid & 15;
    const int ty  = tid >> 4;
    const int m0  = blockIdx.y * 128;
    const int n0  = blockIdx.x * 128;
    const int lr  = tid >> 2;          // 0..63
    const int lc  = (tid & 3) * 4;     // 0,4,8,12

    const float* Ap = A + (size_t)(m0 + lr) * K + lc;
    const float* Bp = B + (size_t)(n0 + lr) * K + lc;
    const size_t strideA = (size_t)64 * K;

    float acc[8][8];
    #pragma unroll
    for (int i = 0; i < 8; i++)
        #pragma unroll
        for (int j = 0; j < 8; j++) acc[i][j] = 0.f;

    // prologue: tile 0
    {
        float4 a0 = *(const float4*)Ap;
        float4 a1 = *(const float4*)(Ap + strideA);
        float4 b0 = *(const float4*)Bp;
        float4 b1 = *(const float4*)(Bp + strideA);
        As[0][lc+0][lr]    = a0.x; As[0][lc+1][lr]    = a0.y; As[0][lc+2][lr]    = a0.z; As[0][lc+3][lr]    = a0.w;
        As[0][lc+0][lr+64] = a1.x; As[0][lc+1][lr+64] = a1.y; As[0][lc+2][lr+64] = a1.z; As[0][lc+3][lr+64] = a1.w;
        Bs[0][lc+0][lr]    = b0.x; Bs[0][lc+1][lr]    = b0.y; Bs[0][lc+2][lr]    = b0.z; Bs[0][lc+3][lr]    = b0.w;
        Bs[0][lc+0][lr+64] = b1.x; Bs[0][lc+1][lr+64] = b1.y; Bs[0][lc+2][lr+64] = b1.z; Bs[0][lc+3][lr+64] = b1.w;
    }
    __syncthreads();

    const int KT = K >> 4;
    for (int kt = 0; kt < KT; ++kt) {
        const int buf = kt & 1;
        float4 na0, na1, nb0, nb1;
        const bool more = (kt + 1) < KT;
        if (more) {
            const float* Ap2 = Ap + (kt + 1) * 16;
            const float* Bp2 = Bp + (kt + 1) * 16;
            na0 = *(const float4*)Ap2;
            na1 = *(const float4*)(Ap2 + strideA);
            nb0 = *(const float4*)Bp2;
            nb1 = *(const float4*)(Bp2 + strideA);
        }
        #pragma unroll
        for (int kk = 0; kk < 16; kk++) {
            float4 af0 = *(const float4*)(&As[buf][kk][ty * 4]);
            float4 af1 = *(const float4*)(&As[buf][kk][64 + ty * 4]);
            float4 bf0 = *(const float4*)(&Bs[buf][kk][tx * 4]);
            float4 bf1 = *(const float4*)(&Bs[buf][kk][64 + tx * 4]);
            float av[8] = {af0.x, af0.y, af0.z, af0.w, af1.x, af1.y, af1.z, af1.w};
            float bv[8] = {bf0.x, bf0.y, bf0.z, bf0.w, bf1.x, bf1.y, bf1.z, bf1.w};
            #pragma unroll
            for (int i = 0; i < 8; i++)
                #pragma unroll
                for (int j = 0; j < 8; j++)
                    acc[i][j] = fmaf(av[i], bv[j], acc[i][j]);
        }
        if (more) {
            const int nb = buf ^ 1;
            As[nb][lc+0][lr]    = na0.x; As[nb][lc+1][lr]    = na0.y; As[nb][lc+2][lr]    = na0.z; As[nb][lc+3][lr]    = na0.w;
            As[nb][lc+0][lr+64] = na1.x; As[nb][lc+1][lr+64] = na1.y; As[nb][lc+2][lr+64] = na1.z; As[nb][lc+3][lr+64] = na1.w;
            Bs[nb][lc+0][lr]    = nb0.x; Bs[nb][lc+1][lr]    = nb0.y; Bs[nb][lc+2][lr]    = nb0.z; Bs[nb][lc+3][lr]    = nb0.w;
            Bs[nb][lc+0][lr+64] = nb1.x; Bs[nb][lc+1][lr+64] = nb1.y; Bs[nb][lc+2][lr+64] = nb1.z; Bs[nb][lc+3][lr+64] = nb1.w;
            __syncthreads();
        }
    }

    float bv0[4] = {0.f, 0.f, 0.f, 0.f}, bv1[4] = {0.f, 0.f, 0.f, 0.f};
    if (bias) {
        #pragma unroll
        for (int j = 0; j < 4; j++) {
            bv0[j] = bias[n0 + tx * 4 + j];
            bv1[j] = bias[n0 + 64 + tx * 4 + j];
        }
    }
    #pragma unroll
    for (int i = 0; i < 8; i++) {
        const int m = m0 + ((i < 4) ? (ty * 4 + i) : (64 + ty * 4 + (i - 4)));
        float* crow = C + (size_t)m * N + n0;
        float4 o0 = make_float4(acc[i][0] + bv0[0], acc[i][1] + bv0[1],
                                acc[i][2] + bv0[2], acc[i][3] + bv0[3]);
        float4 o1 = make_float4(acc[i][4] + bv1[0], acc[i][5] + bv1[1],
                                acc[i][6] + bv1[2], acc[i][7] + bv1[3]);
        *(float4*)(crow + tx * 4)      = o0;
        *(float4*)(crow + 64 + tx * 4) = o1;
    }
}

// ---------------------------------------------------------------------------
// K/V projection: out[b][h][t][d] = sum_c ehs[b, toff+t, c] * W[h*64+d, c]
// One launch handles a weight pair (W0->out0, W1->out1) via blockIdx.z.
// BM=64, BN=64 (= one head), BK=16, 256 threads, 4x4 per thread. M masked.
// ---------------------------------------------------------------------------
__global__ __launch_bounds__(256)
void kv_gemm(const float* __restrict__ ehs,
             const float* __restrict__ W0, const float* __restrict__ W1,
             float* __restrict__ out0, float* __restrict__ out1,
             int rows, int toff)
{
    __shared__ float As[16][64];
    __shared__ float Bs[16][64];

    const int Mtot = BATCH * rows;
    const float* W = blockIdx.z ? W1 : W0;
    float* outp    = blockIdx.z ? out1 : out0;
    const int m0 = blockIdx.x * 64;
    const int h  = blockIdx.y;
    const int tid = threadIdx.x;
    const int tx = tid & 15, ty = tid >> 4;
    const int lr = tid >> 2, lc = (tid & 3) * 4;

    const float* arow = nullptr;
    const int gr = m0 + lr;
    if (gr < Mtot) {
        const int bb = gr / rows, t = gr - bb * rows;
        arow = ehs + (size_t)(bb * TTOT + toff + t) * CDIM + lc;
    }
    const float* brow = W + (size_t)(h * 64 + lr) * CDIM + lc;

    float acc[4][4] = {};
    for (int kt = 0; kt < CDIM / 16; ++kt) {
        float4 av = arow ? *(const float4*)(arow + kt * 16) : make_float4(0.f, 0.f, 0.f, 0.f);
        float4 bv = *(const float4*)(brow + kt * 16);
        __syncthreads();
        As[lc+0][lr] = av.x; As[lc+1][lr] = av.y; As[lc+2][lr] = av.z; As[lc+3][lr] = av.w;
        Bs[lc+0][lr] = bv.x; Bs[lc+1][lr] = bv.y; Bs[lc+2][lr] = bv.z; Bs[lc+3][lr] = bv.w;
        __syncthreads();
        #pragma unroll
        for (int kk = 0; kk < 16; kk++) {
            float4 a  = *(const float4*)(&As[kk][ty * 4]);
            float4 b4 = *(const float4*)(&Bs[kk][tx * 4]);
            float avv[4] = {a.x, a.y, a.z, a.w};
            float bvv[4] = {b4.x, b4.y, b4.z, b4.w};
            #pragma unroll
            for (int i = 0; i < 4; i++)
                #pragma unroll
                for (int j = 0; j < 4; j++)
                    acc[i][j] = fmaf(avv[i], bvv[j], acc[i][j]);
        }
    }
    #pragma unroll
    for (int i = 0; i < 4; i++) {
        const int gr2 = m0 + ty * 4 + i;
        if (gr2 < Mtot) {
            const int bb = gr2 / rows, t = gr2 - bb * rows;
            float4 o = make_float4(acc[i][0], acc[i][1], acc[i][2], acc[i][3]);
            *(float4*)(outp + (size_t)((bb * NHEADS + h) * rows + t) * HDIM + tx * 4) = o;
        }
    }
}

// ---------------------------------------------------------------------------
// Fused attention. One block = 64 queries for one (b, h).
// All keys fit in smem (77 text / 20 ip). Blend is computed by running the
// score/softmax/PV phase multiple times with different (q,k) but the same V,
// accumulating with the blend weight folded into the softmax normalization.
//   b even: out = softmax(q_b k_b) @ v_b
//   b odd : out = 0.5*(P_b + P_{b-1}) @ v_b + 0.5*(ipP_b + ipP_{b-1}) @ ipv_b
// ---------------------------------------------------------------------------
#define ATTN_SMEM ((64*65 + 64*81 + 77*64 + 64*81) * 4)

__global__ __launch_bounds__(256)
void attn_kernel()
{
    extern __shared__ float sm[];
    float* Qt = sm;                 // [64 d][65]   (q transposed, padded)
    float* Kt = Qt + 64 * 65;       // [64 d][81]   (k transposed, padded, zero-filled t>=nt)
    float* Vs = Kt + 64 * 81;       // [77 t][64 d]
    float* Ss = Vs + 77 * 64;       // [64 q][81 t] (scores -> probs)

    const int s0 = blockIdx.x * 64;
    const int h  = blockIdx.y;
    const int b  = blockIdx.z;
    const int tid = threadIdx.x;
    const int tx = tid & 15;        // -> 5 t's (scores), 4 d's (PV)
    const int ty = tid >> 4;        // -> 4 q's

    float acc[4][4] = {};

    auto load_v = [&](const float* vg, int nt) {
        __syncthreads();
        for (int i = tid; i < nt * 64; i += 256) Vs[i] = vg[i];
    };

    auto phase = [&](const float* qg, const float* kg, int nt, float w) {
        __syncthreads();
        for (int i = tid; i < 64 * 64; i += 256) {
            const int q = i >> 6, d = i & 63;
            Qt[d * 65 + q] = qg[(size_t)q * HID + d];
        }
        for (int i = tid; i < 80 * 64; i += 256) {
            const int t = i >> 6, d = i & 63;
            Kt[d * 81 + t] = (t < nt) ? kg[t * 64 + d] : 0.f;
        }
        __syncthreads();

        // scores: S[q][t] = scale * dot_d(Q, K)
        if (tx * 5 < nt) {
            float sacc[4][5];
            #pragma unroll
            for (int i = 0; i < 4; i++)
                #pragma unroll
                for (int j = 0; j < 5; j++) sacc[i][j] = 0.f;
            for (int d = 0; d < 64; d++) {
                const float q0 = Qt[d * 65 + ty * 4 + 0];
                const float q1 = Qt[d * 65 + ty * 4 + 1];
                const float q2 = Qt[d * 65 + ty * 4 + 2];
                const float q3 = Qt[d * 65 + ty * 4 + 3];
                #pragma unroll
                for (int j = 0; j < 5; j++) {
                    const float kv = Kt[d * 81 + tx * 5 + j];
                    sacc[0][j] = fmaf(q0, kv, sacc[0][j]);
                    sacc[1][j] = fmaf(q1, kv, sacc[1][j]);
                    sacc[2][j] = fmaf(q2, kv, sacc[2][j]);
                    sacc[3][j] = fmaf(q3, kv, sacc[3][j]);
                }
            }
            #pragma unroll
            for (int j = 0; j < 5; j++) {
                const int t = tx * 5 + j;
                if (t < nt) {
                    #pragma unroll
                    for (int i = 0; i < 4; i++)
                        Ss[(ty * 4 + i) * 81 + t] = sacc[i][j] * ATTN_SCALE;
                }
            }
        }
        __syncthreads();

        // softmax (4 threads per row), weight w folded into normalization
        {
            const int row = tid >> 2, sub = tid & 3;
            float* srow = Ss + row * 81;
            float m = -1e30f;
            for (int t = sub; t < nt; t += 4) m = fmaxf(m, srow[t]);
            m = fmaxf(m, __shfl_xor_sync(0xffffffffu, m, 1));
            m = fmaxf(m, __shfl_xor_sync(0xffffffffu, m, 2));
            float l = 0.f;
            for (int t = sub; t < nt; t += 4) {
                const float e = __expf(srow[t] - m);
                srow[t] = e;
                l += e;
            }
            l += __shfl_xor_sync(0xffffffffu, l, 1);
            l += __shfl_xor_sync(0xffffffffu, l, 2);
            const float inv = w / l;
            for (int t = sub; t < nt; t += 4) srow[t] *= inv;
        }
        __syncthreads();

        // PV accumulate
        for (int t = 0; t < nt; t++) {
            const float4 v = *(const float4*)(Vs + t * 64 + tx * 4);
            #pragma unroll
            for (int i = 0; i < 4; i++) {
                const float p = Ss[(ty * 4 + i) * 81 + t];
                acc[i][0] = fmaf(p, v.x, acc[i][0]);
                acc[i][1] = fmaf(p, v.y, acc[i][1]);
                acc[i][2] = fmaf(p, v.z, acc[i][2]);
                acc[i][3] = fmaf(p, v.w, acc[i][3]);
            }
        }
    };

    const float* qb = g_q + (size_t)(b * SEQ + s0) * HID + h * HDIM;
    const float* kb = g_k + (size_t)(b * NHEADS + h) * TTXT * HDIM;
    const float* vb = g_v + (size_t)(b * NHEADS + h) * TTXT * HDIM;
    const bool odd = (b & 1);

    load_v(vb, TTXT);
    phase(qb, kb, TTXT, odd ? 0.5f : 1.0f);
    if (odd) {
        const float* qa = g_q + (size_t)((b - 1) * SEQ + s0) * HID + h * HDIM;
        phase(qa, g_k + (size_t)((b - 1) * NHEADS + h) * TTXT * HDIM, TTXT, 0.5f);
        load_v(g_ipv + (size_t)(b * NHEADS + h) * TIP * HDIM, TIP);
        phase(qb, g_ipk + (size_t)(b * NHEADS + h) * TIP * HDIM, TIP, 0.5f);
        phase(qa, g_ipk + (size_t)((b - 1) * NHEADS + h) * TIP * HDIM, TIP, 0.5f);
    }

    float* op = g_attn + (size_t)(b * SEQ + s0) * HID + h * HDIM;
    #pragma unroll
    for (int i = 0; i < 4; i++) {
        float4 o = make_float4(acc[i][0], acc[i][1], acc[i][2], acc[i][3]);
        *(float4*)(op + (size_t)(ty * 4 + i) * HID + tx * 4) = o;
    }
}

// ---------------------------------------------------------------------------
extern "C" void kernel_launch(void* const* d_in, const int* in_sizes, int n_in,
                              void* d_out, int out_size)
{
    const float* hs   = (const float*)d_in[0];
    const float* ehs  = (const float*)d_in[1];
    const float* Wq   = (const float*)d_in[2];
    const float* Wk   = (const float*)d_in[3];
    const float* Wv   = (const float*)d_in[4];
    const float* Wkip = (const float*)d_in[5];
    const float* Wvip = (const float*)d_in[6];
    const float* Wo   = (const float*)d_in[7];
    const float* bo   = (const float*)d_in[8];
    float* out = (float*)d_out;

    float *qp, *ap, *kp, *vp, *ikp, *ivp;
    cudaGetSymbolAddress((void**)&qp,  g_q);
    cudaGetSymbolAddress((void**)&ap,  g_attn);
    cudaGetSymbolAddress((void**)&kp,  g_k);
    cudaGetSymbolAddress((void**)&vp,  g_v);
    cudaGetSymbolAddress((void**)&ikp, g_ipk);
    cudaGetSymbolAddress((void**)&ivp, g_ipv);

    cudaFuncSetAttribute(attn_kernel, cudaFuncAttributeMaxDynamicSharedMemorySize, ATTN_SMEM);

    const dim3 gBig(HID / 128, (BATCH * SEQ) / 128);   // (10, 128)

    // 1) Q = hs @ Wq^T
    sgemm_nt_128<<<gBig, 256>>>(hs, Wq, nullptr, qp, BATCH * SEQ, HID, HID);

    // 2) K/V and ip-K/ip-V projections (head-major outputs)
    kv_gemm<<<dim3(5, NHEADS, 2), 256>>>(ehs, Wk,   Wv,   kp,  vp,  TTXT, 0);
    kv_gemm<<<dim3(2, NHEADS, 2), 256>>>(ehs, Wkip, Wvip, ikp, ivp, TIP,  TTXT);

    // 3) fused attention (text + ip branches, cross-batch blend)
    attn_kernel<<<dim3(SEQ / 64, NHEADS, BATCH), 256, ATTN_SMEM>>>();

    // 4) out = attn @ Wo^T + bo
    sgemm_nt_128<<<gBig, 256>>>(ap, Wo, bo, out, BATCH * SEQ, HID, HID);
}

// round 16
// speedup vs baseline: 1.0019x; 1.0007x over previous
#include <cuda_runtime.h>
#include <math.h>

#define BATCH   4
#define SEQ     4096
#define HID     1280
#define NHEADS  20
#define HDIM    64
#define CDIM    2048
#define TTXT    77
#define TIP     20
#define TTOT    97
#define ATTN_SCALE 0.125f

// Scratch (device globals: no cudaMalloc allowed)
__device__ float g_q   [BATCH*SEQ*HID];            // Q projection
__device__ float g_attn[BATCH*SEQ*HID];            // attention output (pre-Wo)
__device__ float g_k   [BATCH*NHEADS*TTXT*HDIM];   // K heads  [b][h][t][d]
__device__ float g_v   [BATCH*NHEADS*TTXT*HDIM];   // V heads
__device__ float g_ipk [BATCH*NHEADS*TIP*HDIM];    // ip-K heads
__device__ float g_ipv [BATCH*NHEADS*TIP*HDIM];    // ip-V heads

// ---------------------------------------------------------------------------
// SGEMM (NT): C[m][n] = sum_k A[m*K+k] * B[n*K+k] (+ bias[n])
// 128x128 tile, BK=16, 256 threads, 8x8 per thread, double-buffered smem.
// Requires M%128==0, N%128==0, K%16==0.
// ---------------------------------------------------------------------------
__global__ __launch_bounds__(256)
void sgemm_nt_128(const float* __restrict__ A, const float* __restrict__ B,
                  const float* __restrict__ bias, float* __restrict__ C,
                  int M, int N, int K)
{
    __shared__ float As[2][16][128];
    __shared__ float Bs[2][16][128];

    const int tid = threadIdx.x;
    const int tx  = tid & 15;
    const int ty  = tid >> 4;
    const int m0  = blockIdx.y * 128;
    const int n0  = blockIdx.x * 128;
    const int lr  = tid >> 2;          // 0..63
    const int lc  = (tid & 3) * 4;     // 0,4,8,12

    const float* Ap = A + (size_t)(m0 + lr) * K + lc;
    const float* Bp = B + (size_t)(n0 + lr) * K + lc;
    const size_t strideA = (size_t)64 * K;

    float acc[8][8];
    #pragma unroll
    for (int i = 0; i < 8; i++)
        #pragma unroll
        for (int j = 0; j < 8; j++) acc[i][j] = 0.f;

    // prologue: tile 0
    {
        float4 a0 = *(const float4*)Ap;
        float4 a1 = *(const float4*)(Ap + strideA);
        float4 b0 = *(const float4*)Bp;
        float4 b1 = *(const float4*)(Bp + strideA);
        As[0][lc+0][lr]    = a0.x; As[0][lc+1][lr]    = a0.y; As[0][lc+2][lr]    = a0.z; As[0][lc+3][lr]    = a0.w;
        As[0][lc+0][lr+64] = a1.x; As[0][lc+1][lr+64] = a1.y; As[0][lc+2][lr+64] = a1.z; As[0][lc+3][lr+64] = a1.w;
        Bs[0][lc+0][lr]    = b0.x; Bs[0][lc+1][lr]    = b0.y; Bs[0][lc+2][lr]    = b0.z; Bs[0][lc+3][lr]    = b0.w;
        Bs[0][lc+0][lr+64] = b1.x; Bs[0][lc+1][lr+64] = b1.y; Bs[0][lc+2][lr+64] = b1.z; Bs[0][lc+3][lr+64] = b1.w;
    }
    __syncthreads();

    const int KT = K >> 4;
    for (int kt = 0; kt < KT; ++kt) {
        const int buf = kt & 1;
        float4 na0, na1, nb0, nb1;
        const bool more = (kt + 1) < KT;
        if (more) {
            const float* Ap2 = Ap + (kt + 1) * 16;
            const float* Bp2 = Bp + (kt + 1) * 16;
            na0 = *(const float4*)Ap2;
            na1 = *(const float4*)(Ap2 + strideA);
            nb0 = *(const float4*)Bp2;
            nb1 = *(const float4*)(Bp2 + strideA);
        }
        #pragma unroll
        for (int kk = 0; kk < 16; kk++) {
            float4 af0 = *(const float4*)(&As[buf][kk][ty * 4]);
            float4 af1 = *(const float4*)(&As[buf][kk][64 + ty * 4]);
            float4 bf0 = *(const float4*)(&Bs[buf][kk][tx * 4]);
            float4 bf1 = *(const float4*)(&Bs[buf][kk][64 + tx * 4]);
            float av[8] = {af0.x, af0.y, af0.z, af0.w, af1.x, af1.y, af1.z, af1.w};
            float bv[8] = {bf0.x, bf0.y, bf0.z, bf0.w, bf1.x, bf1.y, bf1.z, bf1.w};
            #pragma unroll
            for (int i = 0; i < 8; i++)
                #pragma unroll
                for (int j = 0; j < 8; j++)
                    acc[i][j] = fmaf(av[i], bv[j], acc[i][j]);
        }
        if (more) {
            const int nb = buf ^ 1;
            As[nb][lc+0][lr]    = na0.x; As[nb][lc+1][lr]    = na0.y; As[nb][lc+2][lr]    = na0.z; As[nb][lc+3][lr]    = na0.w;
            As[nb][lc+0][lr+64] = na1.x; As[nb][lc+1][lr+64] = na1.y; As[nb][lc+2][lr+64] = na1.z; As[nb][lc+3][lr+64] = na1.w;
            Bs[nb][lc+0][lr]    = nb0.x; Bs[nb][lc+1][lr]    = nb0.y; Bs[nb][lc+2][lr]    = nb0.z; Bs[nb][lc+3][lr]    = nb0.w;
            Bs[nb][lc+0][lr+64] = nb1.x; Bs[nb][lc+1][lr+64] = nb1.y; Bs[nb][lc+2][lr+64] = nb1.z; Bs[nb][lc+3][lr+64] = nb1.w;
            __syncthreads();
        }
    }

    float bv0[4] = {0.f, 0.f, 0.f, 0.f}, bv1[4] = {0.f, 0.f, 0.f, 0.f};
    if (bias) {
        #pragma unroll
        for (int j = 0; j < 4; j++) {
            bv0[j] = bias[n0 + tx * 4 + j];
            bv1[j] = bias[n0 + 64 + tx * 4 + j];
        }
    }
    #pragma unroll
    for (int i = 0; i < 8; i++) {
        const int m = m0 + ((i < 4) ? (ty * 4 + i) : (64 + ty * 4 + (i - 4)));
        float* crow = C + (size_t)m * N + n0;
        float4 o0 = make_float4(acc[i][0] + bv0[0], acc[i][1] + bv0[1],
                                acc[i][2] + bv0[2], acc[i][3] + bv0[3]);
        float4 o1 = make_float4(acc[i][4] + bv1[0], acc[i][5] + bv1[1],
                                acc[i][6] + bv1[2], acc[i][7] + bv1[3]);
        *(float4*)(crow + tx * 4)      = o0;
        *(float4*)(crow + 64 + tx * 4) = o1;
    }
}

// ---------------------------------------------------------------------------
// K/V projection: out[b][h][t][d] = sum_c ehs[b, toff+t, c] * W[h*64+d, c]
// One launch handles a weight pair (W0->out0, W1->out1) via blockIdx.z.
// BM=64, BN=64 (= one head), BK=16, 256 threads, 4x4 per thread. M masked.
// ---------------------------------------------------------------------------
__global__ __launch_bounds__(256)
void kv_gemm(const float* __restrict__ ehs,
             const float* __restrict__ W0, const float* __restrict__ W1,
             float* __restrict__ out0, float* __restrict__ out1,
             int rows, int toff)
{
    __shared__ float As[16][64];
    __shared__ float Bs[16][64];

    const int Mtot = BATCH * rows;
    const float* W = blockIdx.z ? W1 : W0;
    float* outp    = blockIdx.z ? out1 : out0;
    const int m0 = blockIdx.x * 64;
    const int h  = blockIdx.y;
    const int tid = threadIdx.x;
    const int tx = tid & 15, ty = tid >> 4;
    const int lr = tid >> 2, lc = (tid & 3) * 4;

    const float* arow = nullptr;
    const int gr = m0 + lr;
    if (gr < Mtot) {
        const int bb = gr / rows, t = gr - bb * rows;
        arow = ehs + (size_t)(bb * TTOT + toff + t) * CDIM + lc;
    }
    const float* brow = W + (size_t)(h * 64 + lr) * CDIM + lc;

    float acc[4][4] = {};
    for (int kt = 0; kt < CDIM / 16; ++kt) {
        float4 av = arow ? *(const float4*)(arow + kt * 16) : make_float4(0.f, 0.f, 0.f, 0.f);
        float4 bv = *(const float4*)(brow + kt * 16);
        __syncthreads();
        As[lc+0][lr] = av.x; As[lc+1][lr] = av.y; As[lc+2][lr] = av.z; As[lc+3][lr] = av.w;
        Bs[lc+0][lr] = bv.x; Bs[lc+1][lr] = bv.y; Bs[lc+2][lr] = bv.z; Bs[lc+3][lr] = bv.w;
        __syncthreads();
        #pragma unroll
        for (int kk = 0; kk < 16; kk++) {
            float4 a  = *(const float4*)(&As[kk][ty * 4]);
            float4 b4 = *(const float4*)(&Bs[kk][tx * 4]);
            float avv[4] = {a.x, a.y, a.z, a.w};
            float bvv[4] = {b4.x, b4.y, b4.z, b4.w};
            #pragma unroll
            for (int i = 0; i < 4; i++)
                #pragma unroll
                for (int j = 0; j < 4; j++)
                    acc[i][j] = fmaf(avv[i], bvv[j], acc[i][j]);
        }
    }
    #pragma unroll
    for (int i = 0; i < 4; i++) {
        const int gr2 = m0 + ty * 4 + i;
        if (gr2 < Mtot) {
            const int bb = gr2 / rows, t = gr2 - bb * rows;
            float4 o = make_float4(acc[i][0], acc[i][1], acc[i][2], acc[i][3]);
            *(float4*)(outp + (size_t)((bb * NHEADS + h) * rows + t) * HDIM + tx * 4) = o;
        }
    }
}

// ---------------------------------------------------------------------------
// Fused attention. One block = 64 queries for one (b, h).
// All keys fit in smem (77 text / 20 ip). Blend is computed by running the
// score/softmax/PV phase multiple times with different (q,k) but the same V,
// accumulating with the blend weight folded into the softmax normalization.
//   b even: out = softmax(q_b k_b) @ v_b
//   b odd : out = 0.5*(P_b + P_{b-1}) @ v_b + 0.5*(ipP_b + ipP_{b-1}) @ ipv_b
// ---------------------------------------------------------------------------
#define ATTN_SMEM ((64*65 + 64*81 + 77*64 + 64*81) * 4)

__global__ __launch_bounds__(256)
void attn_kernel()
{
    extern __shared__ float sm[];
    float* Qt = sm;                 // [64 d][65]   (q transposed, padded)
    float* Kt = Qt + 64 * 65;       // [64 d][81]   (k transposed, padded, zero-filled t>=nt)
    float* Vs = Kt + 64 * 81;       // [77 t][64 d]
    float* Ss = Vs + 77 * 64;       // [64 q][81 t] (scores -> probs)

    const int s0 = blockIdx.x * 64;
    const int h  = blockIdx.y;
    const int b  = blockIdx.z;
    const int tid = threadIdx.x;
    const int tx = tid & 15;        // -> 5 t's (scores), 4 d's (PV)
    const int ty = tid >> 4;        // -> 4 q's

    float acc[4][4] = {};

    auto load_v = [&](const float* vg, int nt) {
        __syncthreads();
        for (int i = tid; i < nt * 64; i += 256) Vs[i] = vg[i];
    };

    auto phase = [&](const float* qg, const float* kg, int nt, float w) {
        __syncthreads();
        for (int i = tid; i < 64 * 64; i += 256) {
            const int q = i >> 6, d = i & 63;
            Qt[d * 65 + q] = qg[(size_t)q * HID + d];
        }
        for (int i = tid; i < 80 * 64; i += 256) {
            const int t = i >> 6, d = i & 63;
            Kt[d * 81 + t] = (t < nt) ? kg[t * 64 + d] : 0.f;
        }
        __syncthreads();

        // scores: S[q][t] = scale * dot_d(Q, K)
        if (tx * 5 < nt) {
            float sacc[4][5];
            #pragma unroll
            for (int i = 0; i < 4; i++)
                #pragma unroll
                for (int j = 0; j < 5; j++) sacc[i][j] = 0.f;
            for (int d = 0; d < 64; d++) {
                const float q0 = Qt[d * 65 + ty * 4 + 0];
                const float q1 = Qt[d * 65 + ty * 4 + 1];
                const float q2 = Qt[d * 65 + ty * 4 + 2];
                const float q3 = Qt[d * 65 + ty * 4 + 3];
                #pragma unroll
                for (int j = 0; j < 5; j++) {
                    const float kv = Kt[d * 81 + tx * 5 + j];
                    sacc[0][j] = fmaf(q0, kv, sacc[0][j]);
                    sacc[1][j] = fmaf(q1, kv, sacc[1][j]);
                    sacc[2][j] = fmaf(q2, kv, sacc[2][j]);
                    sacc[3][j] = fmaf(q3, kv, sacc[3][j]);
                }
            }
            #pragma unroll
            for (int j = 0; j < 5; j++) {
                const int t = tx * 5 + j;
                if (t < nt) {
                    #pragma unroll
                    for (int i = 0; i < 4; i++)
                        Ss[(ty * 4 + i) * 81 + t] = sacc[i][j] * ATTN_SCALE;
                }
            }
        }
        __syncthreads();

        // softmax (4 threads per row), weight w folded into normalization
        {
            const int row = tid >> 2, sub = tid & 3;
            float* srow = Ss + row * 81;
            float m = -1e30f;
            for (int t = sub; t < nt; t += 4) m = fmaxf(m, srow[t]);
            m = fmaxf(m, __shfl_xor_sync(0xffffffffu, m, 1));
            m = fmaxf(m, __shfl_xor_sync(0xffffffffu, m, 2));
            float l = 0.f;
            for (int t = sub; t < nt; t += 4) {
                const float e = __expf(srow[t] - m);
                srow[t] = e;
                l += e;
            }
            l += __shfl_xor_sync(0xffffffffu, l, 1);
            l += __shfl_xor_sync(0xffffffffu, l, 2);
            const float inv = w / l;
            for (int t = sub; t < nt; t += 4) srow[t] *= inv;
        }
        __syncthreads();

        // PV accumulate
        for (int t = 0; t < nt; t++) {
            const float4 v = *(const float4*)(Vs + t * 64 + tx * 4);
            #pragma unroll
            for (int i = 0; i < 4; i++) {
                const float p = Ss[(ty * 4 + i) * 81 + t];
                acc[i][0] = fmaf(p, v.x, acc[i][0]);
                acc[i][1] = fmaf(p, v.y, acc[i][1]);
                acc[i][2] = fmaf(p, v.z, acc[i][2]);
                acc[i][3] = fmaf(p, v.w, acc[i][3]);
            }
        }
    };

    const float* qb = g_q + (size_t)(b * SEQ + s0) * HID + h * HDIM;
    const float* kb = g_k + (size_t)(b * NHEADS + h) * TTXT * HDIM;
    const float* vb = g_v + (size_t)(b * NHEADS + h) * TTXT * HDIM;
    const bool odd = (b & 1);

    load_v(vb, TTXT);
    phase(qb, kb, TTXT, odd ? 0.5f : 1.0f);
    if (odd) {
        const float* qa = g_q + (size_t)((b - 1) * SEQ + s0) * HID + h * HDIM;
        phase(qa, g_k + (size_t)((b - 1) * NHEADS + h) * TTXT * HDIM, TTXT, 0.5f);
        load_v(g_ipv + (size_t)(b * NHEADS + h) * TIP * HDIM, TIP);
        phase(qb, g_ipk + (size_t)(b * NHEADS + h) * TIP * HDIM, TIP, 0.5f);
        phase(qa, g_ipk + (size_t)((b - 1) * NHEADS + h) * TIP * HDIM, TIP, 0.5f);
    }

    float* op = g_attn + (size_t)(b * SEQ + s0) * HID + h * HDIM;
    #pragma unroll
    for (int i = 0; i < 4; i++) {
        float4 o = make_float4(acc[i][0], acc[i][1], acc[i][2], acc[i][3]);
        *(float4*)(op + (size_t)(ty * 4 + i) * HID + tx * 4) = o;
    }
}

// ---------------------------------------------------------------------------
extern "C" void kernel_launch(void* const* d_in, const int* in_sizes, int n_in,
                              void* d_out, int out_size)
{
    const float* hs   = (const float*)d_in[0];
    const float* ehs  = (const float*)d_in[1];
    const float* Wq   = (const float*)d_in[2];
    const float* Wk   = (const float*)d_in[3];
    const float* Wv   = (const float*)d_in[4];
    const float* Wkip = (const float*)d_in[5];
    const float* Wvip = (const float*)d_in[6];
    const float* Wo   = (const float*)d_in[7];
    const float* bo   = (const float*)d_in[8];
    float* out = (float*)d_out;

    float *qp, *ap, *kp, *vp, *ikp, *ivp;
    cudaGetSymbolAddress((void**)&qp,  g_q);
    cudaGetSymbolAddress((void**)&ap,  g_attn);
    cudaGetSymbolAddress((void**)&kp,  g_k);
    cudaGetSymbolAddress((void**)&vp,  g_v);
    cudaGetSymbolAddress((void**)&ikp, g_ipk);
    cudaGetSymbolAddress((void**)&ivp, g_ipv);

    cudaFuncSetAttribute(attn_kernel, cudaFuncAttributeMaxDynamicSharedMemorySize, ATTN_SMEM);

    const dim3 gBig(HID / 128, (BATCH * SEQ) / 128);   // (10, 128)

    // 1) Q = hs @ Wq^T
    sgemm_nt_128<<<gBig, 256>>>(hs, Wq, nullptr, qp, BATCH * SEQ, HID, HID);

    // 2) K/V and ip-K/ip-V projections (head-major outputs)
    kv_gemm<<<dim3(5, NHEADS, 2), 256>>>(ehs, Wk,   Wv,   kp,  vp,  TTXT, 0);
    kv_gemm<<<dim3(2, NHEADS, 2), 256>>>(ehs, Wkip, Wvip, ikp, ivp, TIP,  TTXT);

    // 3) fused attention (text + ip branches, cross-batch blend)
    attn_kernel<<<dim3(SEQ / 64, NHEADS, BATCH), 256, ATTN_SMEM>>>();

    // 4) out = attn @ Wo^T + bo
    sgemm_nt_128<<<gBig, 256>>>(ap, Wo, bo, out, BATCH * SEQ, HID, HID);
}